// round 10
// baseline (speedup 1.0000x reference)
#include <cuda_runtime.h>
#include <cuda_fp16.h>

// Problem constants
#define BB 256
#define SS 500
#define EE 128

// ---------------- device-global scratch (no runtime allocs allowed) ----------------
__device__ float  g_inp[SS * BB * EE];     // linear1 output, time-major [s][b][e] (65.5 MB)
__device__ float4 g_W1p[128 * 128];        // W1 packed: [k4][j] -> float4 over 4 consecutive k
__device__ uint2  g_W2p[32 * 128];         // fp16x4 packed [k4][j]
__device__ uint2  g_W3p[32 * 128];
__device__ uint2  g_W4p[64 * 128];
__device__ uint2  g_W5p[64 * 128];
__device__ uint2  g_W6p[128 * 128];

// ---------------- helpers ----------------
__device__ __forceinline__ float4 h4tof4(uint2 w) {
    __half2 a = *reinterpret_cast<__half2*>(&w.x);
    __half2 b = *reinterpret_cast<__half2*>(&w.y);
    float2 fa = __half22float2(a);
    float2 fb = __half22float2(b);
    float4 r; r.x = fa.x; r.y = fa.y; r.z = fb.x; r.w = fb.y;
    return r;
}
__device__ __forceinline__ float sigm(float x) {
    return 1.0f / (1.0f + __expf(-x));
}
__device__ __forceinline__ float tanh_f(float x) {
    // tanh(x) = 1 - 2/(exp(2x)+1); safe at both extremes with __expf
    return 1.0f - 2.0f / (__expf(2.0f * x) + 1.0f);
}

// ---------------- prep: W1 -> float4 [k4][j] ----------------
__global__ void prep_w1(const float* __restrict__ W1) {
    int t = blockIdx.x * blockDim.x + threadIdx.x;
    if (t >= 128 * 128) return;
    int k4 = t >> 7, j = t & 127;
    const float* s = W1 + j * 512 + k4 * 4;
    g_W1p[t] = make_float4(s[0], s[1], s[2], s[3]);
}

// ---------------- prep: W2..W6 -> fp16x4 [k4][j] ----------------
__global__ void prep_half(const float* __restrict__ W2, const float* __restrict__ W3,
                          const float* __restrict__ W4, const float* __restrict__ W5,
                          const float* __restrict__ W6) {
    int t = blockIdx.x * blockDim.x + threadIdx.x;
    if (t >= 40960) return;
    const float* W; uint2* dst; int in_dim; int o = t;
    if (o < 4096)        { W = W2; dst = g_W2p; in_dim = 128; }
    else if (o < 8192)   { o -= 4096;  W = W3; dst = g_W3p; in_dim = 128; }
    else if (o < 16384)  { o -= 8192;  W = W4; dst = g_W4p; in_dim = 256; }
    else if (o < 24576)  { o -= 16384; W = W5; dst = g_W5p; in_dim = 256; }
    else                 { o -= 24576; W = W6; dst = g_W6p; in_dim = 512; }
    int k4 = o >> 7, j = o & 127;
    const float* s = W + j * in_dim + k4 * 4;
    __half2 lo = __floats2half2_rn(s[0], s[1]);
    __half2 hi = __floats2half2_rn(s[2], s[3]);
    uint2 v;
    v.x = *reinterpret_cast<unsigned*>(&lo);
    v.y = *reinterpret_cast<unsigned*>(&hi);
    dst[o] = v;
}

// ---------------- kernel 1: input_data = cat(q_emb, c_e, sd_e, qd_e) @ W1^T + b1 ----------------
// 16 rows per CTA, 256 threads: thread = (j in [0,128), kh in {0,1} = K-half)
__global__ void __launch_bounds__(256) k_input(
    const float* __restrict__ qemb, const int* __restrict__ c,
    const int* __restrict__ sd, const int* __restrict__ qd,
    const float* __restrict__ c_tab, const float* __restrict__ sd_tab,
    const float* __restrict__ qd_tab, const float* __restrict__ b1)
{
    __shared__ float xs[16 * 512];
    __shared__ int   sidx[16][3];
    int tid = threadIdx.x;
    int row0 = blockIdx.x * 16;

    if (tid < 48) {
        int rr = tid / 3, w = tid % 3;
        int row = row0 + rr;
        sidx[rr][w] = (w == 0) ? c[row] : ((w == 1) ? sd[row] : qd[row]);
    }
    __syncthreads();

    float4* xs4 = reinterpret_cast<float4*>(xs);
    const float4 zero4 = make_float4(0.f, 0.f, 0.f, 0.f);
    #pragma unroll
    for (int i = 0; i < 8; i++) {
        int f = tid + i * 256;          // float4 slot in [0, 2048)
        int r = f >> 7, seg = f & 127;  // seg = float4 index within 512-float row
        float4 v;
        if (seg < 32) {
            v = reinterpret_cast<const float4*>(qemb)[(row0 + r) * 32 + seg];
        } else if (seg < 64) {
            int idx = sidx[r][0];
            v = idx ? reinterpret_cast<const float4*>(c_tab)[idx * 32 + (seg - 32)] : zero4;
        } else if (seg < 96) {
            int idx = sidx[r][1];
            v = idx ? reinterpret_cast<const float4*>(sd_tab)[idx * 32 + (seg - 64)] : zero4;
        } else {
            int idx = sidx[r][2];
            v = idx ? reinterpret_cast<const float4*>(qd_tab)[idx * 32 + (seg - 96)] : zero4;
        }
        xs4[f] = v;
    }
    __syncthreads();

    int j = tid & 127, kh = tid >> 7;
    float acc[16];
    #pragma unroll
    for (int r = 0; r < 16; r++) acc[r] = 0.f;
    int kbase = kh * 64;   // float4 k-index base
    for (int k4 = 0; k4 < 64; k4++) {
        float4 w = g_W1p[(kbase + k4) * 128 + j];
        #pragma unroll
        for (int r = 0; r < 16; r++) {
            float4 x = xs4[r * 128 + kbase + k4];
            acc[r] += w.x * x.x + w.y * x.y + w.z * x.z + w.w * x.w;
        }
    }
    __syncthreads();   // done reading xs; reuse as reduction buffer
    if (kh == 1) {
        #pragma unroll
        for (int r = 0; r < 16; r++) xs[r * 128 + j] = acc[r];
    }
    __syncthreads();
    if (kh == 0) {
        float b1j = b1[j];
        #pragma unroll
        for (int r = 0; r < 16; r++) {
            int row = row0 + r;
            float v = acc[r] + xs[r * 128 + j] + b1j;
            int b = row / SS;
            int s = row - b * SS;
            g_inp[(s * BB + b) * EE + j] = v;
        }
    }
}

// ---------------- scan kernel: persistent over 500 steps, 2 batch rows per CTA ----------------
// 256 threads: thread = (j in [0,128), h in {0,1}); each thread handles BOTH rows
// smem: W5 (64KB fp16) + W6 (128KB fp16) resident; W2/W3/W4 streamed from L2 (fp16)
#define SM_W5   0
#define SM_W6   65536
#define SM_KS   196608
#define SM_QQ   197632
#define SM_INS  198656
#define SM_XB4  202752
#define SM_S2   204800
#define SM_S3   205824
#define SM_S4   206848
#define SM_S5   207872
#define SM_P6   208896
#define SM_TOTAL 209920

__global__ void __launch_bounds__(256, 1) k_scan(
    const int* __restrict__ a, const int* __restrict__ sd, const int* __restrict__ qd,
    const float* __restrict__ sd_tab, const float* __restrict__ qd_tab,
    const float* __restrict__ a_tab, const float* __restrict__ knowledge,
    const float* __restrict__ b2, const float* __restrict__ b3,
    const float* __restrict__ b4, const float* __restrict__ b5,
    const float* __restrict__ b6, float* __restrict__ out)
{
    extern __shared__ char sm[];
    uint2* W5s  = reinterpret_cast<uint2*>(sm + SM_W5);   // [64][128]
    uint2* W6s  = reinterpret_cast<uint2*>(sm + SM_W6);   // [128][128]
    float* k_s  = reinterpret_cast<float*>(sm + SM_KS);   // [2][128]
    float* qqb  = reinterpret_cast<float*>(sm + SM_QQ);   // [2][128]
    float* insb = reinterpret_cast<float*>(sm + SM_INS);  // [2][512]
    float* xb4b = reinterpret_cast<float*>(sm + SM_XB4);  // [2][256]
    float* s2b  = reinterpret_cast<float*>(sm + SM_S2);   // [2][128]
    float* s3b  = reinterpret_cast<float*>(sm + SM_S3);
    float* s4b  = reinterpret_cast<float*>(sm + SM_S4);
    float* s5b  = reinterpret_cast<float*>(sm + SM_S5);
    float* p6b  = reinterpret_cast<float*>(sm + SM_P6);

    const float4* qq4  = reinterpret_cast<const float4*>(qqb);
    const float4* ins4 = reinterpret_cast<const float4*>(insb);
    const float4* xb44 = reinterpret_cast<const float4*>(xb4b);

    int tid = threadIdx.x;
    int j = tid & 127, h = tid >> 7;   // h uniform per warp
    int b0 = blockIdx.x * 2;

    for (int i = tid; i < 8192;  i += 256) W5s[i] = g_W5p[i];
    for (int i = tid; i < 16384; i += 256) W6s[i] = g_W6p[i];
    if (h == 0) {
        float kv = knowledge[j];
        k_s[j] = kv; k_s[128 + j] = kv;
    }
    float biasB = h ? b3[j] : b2[j];
    float biasD = h ? b5[j] : b4[j];
    float bias6 = b6[j];
    __syncthreads();

    float y6p0 = 0.f, y6p1 = 0.f;   // E-phase partials held across the sync

    for (int s = 0; s < SS; s++) {
        // ---- Phase A: build qq, ins, a_e half of xcat ----
        if (h == 0) {
            #pragma unroll
            for (int r = 0; r < 2; r++) {
                int b = b0 + r;
                float kv = k_s[r * 128 + j];
                qqb[r * 128 + j] = kv - g_inp[(s * BB + b) * EE + j];
                insb[r * 512 + j] = kv;
                int isd = sd[b * SS + s];
                insb[r * 512 + 256 + j] = isd ? sd_tab[isd * 128 + j] : 0.f;
            }
        } else {
            #pragma unroll
            for (int r = 0; r < 2; r++) {
                int b = b0 + r;
                int ia = a[b * SS + s];
                float av = a_tab[ia * 128 + j];
                insb[r * 512 + 128 + j] = av;
                xb4b[r * 256 + 128 + j] = av;
                int iq = qd[b * SS + s];
                insb[r * 512 + 384 + j] = iq ? qd_tab[iq * 128 + j] : 0.f;
            }
        }
        __syncthreads();

        // ---- Phase B: y2 = W2*qq (h=0) / y3 = W3*qq (h=1), both rows ----
        {
            const uint2* Wp = h ? g_W3p : g_W2p;
            float4 a0 = make_float4(0,0,0,0), a1 = make_float4(0,0,0,0);
            #pragma unroll 8
            for (int k4 = 0; k4 < 32; k4++) {
                float4 w = h4tof4(Wp[k4 * 128 + j]);
                float4 x0 = qq4[k4];
                float4 x1 = qq4[32 + k4];
                a0.x = fmaf(w.x, x0.x, a0.x); a0.y = fmaf(w.y, x0.y, a0.y);
                a0.z = fmaf(w.z, x0.z, a0.z); a0.w = fmaf(w.w, x0.w, a0.w);
                a1.x = fmaf(w.x, x1.x, a1.x); a1.y = fmaf(w.y, x1.y, a1.y);
                a1.z = fmaf(w.z, x1.z, a1.z); a1.w = fmaf(w.w, x1.w, a1.w);
            }
            float y0 = biasB + (a0.x + a0.y) + (a0.z + a0.w);
            float y1 = biasB + (a1.x + a1.y) + (a1.z + a1.w);
            if (h) { s3b[j] = tanh_f(y0); s3b[128 + j] = tanh_f(y1); }
            else   { s2b[j] = sigm(y0);   s2b[128 + j] = sigm(y1); }
        }
        __syncthreads();

        // ---- Phase C: sdft half of xcat ----
        if (h == 0) {
            xb4b[j]       = s2b[j]       * s3b[j];
            xb4b[256 + j] = s2b[128 + j] * s3b[128 + j];
        }
        __syncthreads();

        // ---- Phase D: y4 = W4*xcat (h=0, streamed) / y5 = W5*xcat (h=1, smem) ----
        {
            float4 a0 = make_float4(0,0,0,0), a1 = make_float4(0,0,0,0);
            if (h == 0) {
                #pragma unroll 8
                for (int k4 = 0; k4 < 64; k4++) {
                    float4 w = h4tof4(g_W4p[k4 * 128 + j]);
                    float4 x0 = xb44[k4];
                    float4 x1 = xb44[64 + k4];
                    a0.x = fmaf(w.x, x0.x, a0.x); a0.y = fmaf(w.y, x0.y, a0.y);
                    a0.z = fmaf(w.z, x0.z, a0.z); a0.w = fmaf(w.w, x0.w, a0.w);
                    a1.x = fmaf(w.x, x1.x, a1.x); a1.y = fmaf(w.y, x1.y, a1.y);
                    a1.z = fmaf(w.z, x1.z, a1.z); a1.w = fmaf(w.w, x1.w, a1.w);
                }
                float y0 = biasD + (a0.x + a0.y) + (a0.z + a0.w);
                float y1 = biasD + (a1.x + a1.y) + (a1.z + a1.w);
                s4b[j] = sigm(y0); s4b[128 + j] = sigm(y1);
            } else {
                #pragma unroll 8
                for (int k4 = 0; k4 < 64; k4++) {
                    float4 w = h4tof4(W5s[k4 * 128 + j]);
                    float4 x0 = xb44[k4];
                    float4 x1 = xb44[64 + k4];
                    a0.x = fmaf(w.x, x0.x, a0.x); a0.y = fmaf(w.y, x0.y, a0.y);
                    a0.z = fmaf(w.z, x0.z, a0.z); a0.w = fmaf(w.w, x0.w, a0.w);
                    a1.x = fmaf(w.x, x1.x, a1.x); a1.y = fmaf(w.y, x1.y, a1.y);
                    a1.z = fmaf(w.z, x1.z, a1.z); a1.w = fmaf(w.w, x1.w, a1.w);
                }
                float y0 = biasD + (a0.x + a0.y) + (a0.z + a0.w);
                float y1 = biasD + (a1.x + a1.y) + (a1.z + a1.w);
                s5b[j] = tanh_f(y0); s5b[128 + j] = tanh_f(y1);
            }
        }
        // no sync needed here: s4/s5 consumers are after the E-phase sync

        // ---- Phase E: y6 = W6*ins, K=512 split by h (smem weights) ----
        {
            float4 a0 = make_float4(0,0,0,0), a1 = make_float4(0,0,0,0);
            int kb = h * 64;
            #pragma unroll 8
            for (int k4 = 0; k4 < 64; k4++) {
                float4 w = h4tof4(W6s[(kb + k4) * 128 + j]);
                float4 x0 = ins4[kb + k4];
                float4 x1 = ins4[128 + kb + k4];
                a0.x = fmaf(w.x, x0.x, a0.x); a0.y = fmaf(w.y, x0.y, a0.y);
                a0.z = fmaf(w.z, x0.z, a0.z); a0.w = fmaf(w.w, x0.w, a0.w);
                a1.x = fmaf(w.x, x1.x, a1.x); a1.y = fmaf(w.y, x1.y, a1.y);
                a1.z = fmaf(w.z, x1.z, a1.z); a1.w = fmaf(w.w, x1.w, a1.w);
            }
            y6p0 = (a0.x + a0.y) + (a0.z + a0.w);
            y6p1 = (a1.x + a1.y) + (a1.z + a1.w);
            if (h) { p6b[j] = y6p0; p6b[128 + j] = y6p1; }
        }
        __syncthreads();

        // ---- Finalize: k_new = g*k + (1-g)*pkat ----
        if (h == 0) {
            #pragma unroll
            for (int r = 0; r < 2; r++) {
                float yp = r ? y6p1 : y6p0;
                float y6 = yp + p6b[r * 128 + j] + bias6;
                float g  = sigm(y6);
                float pk = s4b[r * 128 + j] * s5b[r * 128 + j];
                float kv = k_s[r * 128 + j];
                k_s[r * 128 + j] = g * kv + (1.0f - g) * pk;
            }
        }
        // no sync needed: k_s is only read/written by its owning thread;
        // all shared buffers consumed this step were read before the E sync.
    }

    if (h == 0) {
        out[b0 * EE + j]       = sigm(k_s[j]);
        out[(b0 + 1) * EE + j] = sigm(k_s[128 + j]);
    }
}

// ---------------- launch ----------------
extern "C" void kernel_launch(void* const* d_in, const int* in_sizes, int n_in,
                              void* d_out, int out_size) {
    (void)in_sizes; (void)n_in; (void)out_size;
    const int*   q        = (const int*)d_in[0];  (void)q;
    const int*   c        = (const int*)d_in[1];
    const int*   sd       = (const int*)d_in[2];
    const int*   qd       = (const int*)d_in[3];
    const int*   a        = (const int*)d_in[4];
    // d_in[5..8] = qshft, cshft, sdshft, qdshft — unused by the reference
    const float* qemb     = (const float*)d_in[9];
    const float* c_tab    = (const float*)d_in[10];
    const float* sd_tab   = (const float*)d_in[11];
    const float* qd_tab   = (const float*)d_in[12];
    const float* a_tab    = (const float*)d_in[13];
    const float* know     = (const float*)d_in[14];
    const float* W1       = (const float*)d_in[15];
    const float* b1       = (const float*)d_in[16];
    const float* W2       = (const float*)d_in[17];
    const float* b2       = (const float*)d_in[18];
    const float* W3       = (const float*)d_in[19];
    const float* b3       = (const float*)d_in[20];
    const float* W4       = (const float*)d_in[21];
    const float* b4       = (const float*)d_in[22];
    const float* W5       = (const float*)d_in[23];
    const float* b5       = (const float*)d_in[24];
    const float* W6       = (const float*)d_in[25];
    const float* b6       = (const float*)d_in[26];
    float* out = (float*)d_out;

    cudaFuncSetAttribute(k_scan, cudaFuncAttributeMaxDynamicSharedMemorySize, SM_TOTAL);

    prep_w1<<<64, 256>>>(W1);
    prep_half<<<160, 256>>>(W2, W3, W4, W5, W6);
    k_input<<<8000, 256>>>(qemb, c, sd, qd, c_tab, sd_tab, qd_tab, b1);
    k_scan<<<128, 256, SM_TOTAL>>>(a, sd, qd, sd_tab, qd_tab, a_tab, know,
                                   b2, b3, b4, b5, b6, out);
}

// round 12
// speedup vs baseline: 1.8004x; 1.8004x over previous
#include <cuda_runtime.h>
#include <cuda_fp16.h>

#define BB 256
#define SS 500
#define EE 128

// ---------------- device-global scratch (no runtime allocs allowed) ----------------
__device__ __half   g_inp[SS * BB * EE];   // linear1 output, time-major [s][b][e], fp16 (32MB)
__device__ uint2    g_W1h[128 * 128];      // fp16x4 [k4][j] (k in [0,512))
__device__ uint2    g_W2h[32 * 128];       // fp16x4 [k4][j]
__device__ uint2    g_W3h[32 * 128];
__device__ unsigned g_W4q[64 * 128];       // e4m3x4 (x64 scale) [k4][j]
__device__ unsigned g_W5q[64 * 128];
__device__ unsigned g_W6q[128 * 128];

#define W_SCALE 64.0f
#define W_INV   (1.0f / 64.0f)

// ---------------- helpers ----------------
__device__ __forceinline__ float sigm(float x) {
    return 1.0f / (1.0f + __expf(-x));
}
__device__ __forceinline__ float tanh_f(float x) {
    return 1.0f - 2.0f / (__expf(2.0f * x) + 1.0f);
}
__device__ __forceinline__ float hsum4(__half2 a, __half2 b) {
    float2 fa = __half22float2(a), fb = __half22float2(b);
    return (fa.x + fa.y) + (fb.x + fb.y);
}
__device__ __forceinline__ __half2 cvt_e4m3x2(unsigned short v) {
    unsigned r;
    asm("cvt.rn.f16x2.e4m3x2 %0, %1;" : "=r"(r) : "h"(v));
    return *reinterpret_cast<__half2*>(&r);
}
__device__ __forceinline__ unsigned short pack_e4m3x2(float lo, float hi) {
    unsigned short r;
    // cvt d,a,b: a -> upper 8 bits, b -> lower 8 bits
    asm("cvt.rn.satfinite.e4m3x2.f32 %0, %1, %2;" : "=h"(r) : "f"(hi), "f"(lo));
    return r;
}
__device__ __forceinline__ unsigned h2bits(__half2 h) {
    return *reinterpret_cast<unsigned*>(&h);
}
__device__ __forceinline__ __half2 bits2h(unsigned v) {
    return *reinterpret_cast<__half2*>(&v);
}

// ---------------- prep: pack all weights ----------------
__global__ void prep_all(const float* __restrict__ W1, const float* __restrict__ W2,
                         const float* __restrict__ W3, const float* __restrict__ W4,
                         const float* __restrict__ W5, const float* __restrict__ W6) {
    int t = blockIdx.x * blockDim.x + threadIdx.x;
    if (t < 16384) {
        // W1 -> fp16x4 [k4][j], in_dim 512
        int k4 = t >> 7, j = t & 127;
        const float* s = W1 + j * 512 + k4 * 4;
        uint2 v;
        v.x = h2bits(__floats2half2_rn(s[0], s[1]));
        v.y = h2bits(__floats2half2_rn(s[2], s[3]));
        g_W1h[t] = v;
    } else if (t < 24576) {
        int o = t - 16384;
        const float* W = (o < 4096) ? W2 : W3;
        uint2* dst = (o < 4096) ? g_W2h : g_W3h;
        o &= 4095;
        int k4 = o >> 7, j = o & 127;
        const float* s = W + j * 128 + k4 * 4;
        uint2 v;
        v.x = h2bits(__floats2half2_rn(s[0], s[1]));
        v.y = h2bits(__floats2half2_rn(s[2], s[3]));
        dst[o] = v;
    } else if (t < 57344) {
        int o = t - 24576;
        const float* W; unsigned* dst; int in_dim;
        if (o < 8192)        { W = W4; dst = g_W4q; in_dim = 256; }
        else if (o < 16384)  { o -= 8192;  W = W5; dst = g_W5q; in_dim = 256; }
        else                 { o -= 16384; W = W6; dst = g_W6q; in_dim = 512; }
        int k4 = o >> 7, j = o & 127;
        const float* s = W + j * in_dim + k4 * 4;
        unsigned lo = pack_e4m3x2(s[0] * W_SCALE, s[1] * W_SCALE);
        unsigned hi = pack_e4m3x2(s[2] * W_SCALE, s[3] * W_SCALE);
        dst[o] = lo | (hi << 16);
    }
}

// ---------------- kernel 1: input_data = cat(q_emb, c_e, sd_e, qd_e) @ W1^T + b1 ----------------
// 16 rows/CTA, 256 threads: thread = (j in [0,128), kh in {0,1})
__global__ void __launch_bounds__(256) k_input(
    const float* __restrict__ qemb, const int* __restrict__ c,
    const int* __restrict__ sd, const int* __restrict__ qd,
    const float* __restrict__ c_tab, const float* __restrict__ sd_tab,
    const float* __restrict__ qd_tab, const float* __restrict__ b1)
{
    __shared__ __half2 xh[16 * 256];   // 16 rows x 512 halves (16KB)
    __shared__ int     sidx[16][3];
    int tid = threadIdx.x;
    int row0 = blockIdx.x * 16;

    if (tid < 48) {
        int rr = tid / 3, w = tid % 3;
        int row = row0 + rr;
        sidx[rr][w] = (w == 0) ? c[row] : ((w == 1) ? sd[row] : qd[row]);
    }
    __syncthreads();

    const float4 zero4 = make_float4(0.f, 0.f, 0.f, 0.f);
    uint2* xh4 = reinterpret_cast<uint2*>(xh);
    #pragma unroll
    for (int i = 0; i < 8; i++) {
        int f = tid + i * 256;          // float4-slot in [0, 2048)
        int r = f >> 7, seg = f & 127;
        float4 v;
        if (seg < 32) {
            v = reinterpret_cast<const float4*>(qemb)[(row0 + r) * 32 + seg];
        } else if (seg < 64) {
            int idx = sidx[r][0];
            v = idx ? reinterpret_cast<const float4*>(c_tab)[idx * 32 + (seg - 32)] : zero4;
        } else if (seg < 96) {
            int idx = sidx[r][1];
            v = idx ? reinterpret_cast<const float4*>(sd_tab)[idx * 32 + (seg - 64)] : zero4;
        } else {
            int idx = sidx[r][2];
            v = idx ? reinterpret_cast<const float4*>(qd_tab)[idx * 32 + (seg - 96)] : zero4;
        }
        uint2 p;
        p.x = h2bits(__floats2half2_rn(v.x, v.y));
        p.y = h2bits(__floats2half2_rn(v.z, v.w));
        xh4[f] = p;
    }
    __syncthreads();

    int j = tid & 127, kh = tid >> 7;
    float facc[16];
    #pragma unroll
    for (int r = 0; r < 16; r++) facc[r] = 0.f;

    const uint2* Wp = g_W1h + (kh * 64) * 128 + j;
    const uint2* xb = reinterpret_cast<const uint2*>(xh) + kh * 64;

    #pragma unroll
    for (int half = 0; half < 2; half++) {
        __half2 ae[16], ao[16];
        #pragma unroll
        for (int r = 0; r < 16; r++) { ae[r] = bits2h(0u); ao[r] = bits2h(0u); }
        #pragma unroll 4
        for (int k4 = 0; k4 < 32; k4++) {
            int kk = half * 32 + k4;
            uint2 w = Wp[kk * 128];
            __half2 wa = bits2h(w.x), wb = bits2h(w.y);
            #pragma unroll
            for (int r = 0; r < 16; r++) {
                uint2 xv = xb[r * 128 + kk];
                ae[r] = __hfma2(wa, bits2h(xv.x), ae[r]);
                ao[r] = __hfma2(wb, bits2h(xv.y), ao[r]);
            }
        }
        #pragma unroll
        for (int r = 0; r < 16; r++) facc[r] += hsum4(ae[r], ao[r]);
    }
    __syncthreads();   // done reading xh; reuse as reduction buffer
    float* red = reinterpret_cast<float*>(xh);
    if (kh == 1) {
        #pragma unroll
        for (int r = 0; r < 16; r++) red[r * 128 + j] = facc[r];
    }
    __syncthreads();
    if (kh == 0) {
        float b1j = b1[j];
        #pragma unroll
        for (int r = 0; r < 16; r++) {
            int row = row0 + r;
            float v = facc[r] + red[r * 128 + j] + b1j;
            int b = row / SS;
            int s = row - b * SS;
            g_inp[(s * BB + b) * EE + j] = __float2half(v);
        }
    }
}

// ---------------- scan kernel ----------------
// 512 threads: thread = (j in [0,128), group g in {0,1,2,3}); 2 batch rows per CTA.
// All weights smem-resident: W2,W3 fp16; W4,W5,W6 e4m3 (x64 scale). 4 syncs/step.
#define SO_W2   0
#define SO_W3   32768
#define SO_W4   65536
#define SO_W5   98304
#define SO_W6   131072
#define SO_KS   196608
#define SO_QQ   197632
#define SO_INS  198144
#define SO_XC   200192
#define SO_PB   201216
#define SO_PE   205312
#define SM_TOTAL 209408

__global__ void __launch_bounds__(512, 1) k_scan(
    const int* __restrict__ a, const int* __restrict__ sd, const int* __restrict__ qd,
    const float* __restrict__ sd_tab, const float* __restrict__ qd_tab,
    const float* __restrict__ a_tab, const float* __restrict__ knowledge,
    const float* __restrict__ b2, const float* __restrict__ b3,
    const float* __restrict__ b4, const float* __restrict__ b5,
    const float* __restrict__ b6, float* __restrict__ out)
{
    extern __shared__ char sm[];
    uint2*    W2s = reinterpret_cast<uint2*>(sm + SO_W2);     // [32][128]
    uint2*    W3s = reinterpret_cast<uint2*>(sm + SO_W3);
    unsigned* W4s = reinterpret_cast<unsigned*>(sm + SO_W4);  // [64][128]
    unsigned* W5s = reinterpret_cast<unsigned*>(sm + SO_W5);
    unsigned* W6s = reinterpret_cast<unsigned*>(sm + SO_W6);  // [128][128]
    float*    k_s = reinterpret_cast<float*>(sm + SO_KS);     // [2][128]
    __half*   qqh = reinterpret_cast<__half*>(sm + SO_QQ);    // [2][128]
    __half*   insh= reinterpret_cast<__half*>(sm + SO_INS);   // [2][512]
    __half*   xch = reinterpret_cast<__half*>(sm + SO_XC);    // [2][256]
    float*    pB  = reinterpret_cast<float*>(sm + SO_PB);     // [4][2][128] (reused as pD)
    float*    pE  = reinterpret_cast<float*>(sm + SO_PE);     // [4][2][128]

    int tid = threadIdx.x;
    int j = tid & 127, g = tid >> 7;
    int b0 = blockIdx.x * 2;

    // load weights into smem
    for (int i = tid; i < 4096;  i += 512) { W2s[i] = g_W2h[i]; W3s[i] = g_W3h[i]; }
    for (int i = tid; i < 8192;  i += 512) { W4s[i] = g_W4q[i]; W5s[i] = g_W5q[i]; }
    for (int i = tid; i < 16384; i += 512) { W6s[i] = g_W6q[i]; }

    float b2j = b2[j], b3j = b3[j], b4j = b4[j], b5j = b5[j], b6j = b6[j];

    // initial A (s = 0)
    if (g < 2) {
        int r = g, b = b0 + r;
        float kv = knowledge[j];
        k_s[r * 128 + j] = kv;
        float inp = __half2float(g_inp[(0 * BB + b) * EE + j]);
        qqh[r * 128 + j]  = __float2half(kv - inp);
        insh[r * 512 + j] = __float2half(kv);
    } else if (g == 2) {
        #pragma unroll
        for (int r = 0; r < 2; r++) {
            int b = b0 + r;
            int ia = a[b * SS + 0];
            __half av = __float2half(a_tab[ia * 128 + j]);
            insh[r * 512 + 128 + j] = av;
            xch[r * 256 + 128 + j]  = av;
        }
        int isd = sd[b0 * SS + 0];
        insh[256 + j] = isd ? __float2half(sd_tab[isd * 128 + j]) : __half(0.f);
    } else {
        #pragma unroll
        for (int r = 0; r < 2; r++) {
            int b = b0 + r;
            int iq = qd[b * SS + 0];
            insh[r * 512 + 384 + j] = iq ? __float2half(qd_tab[iq * 128 + j]) : __half(0.f);
        }
        int isd = sd[(b0 + 1) * SS + 0];
        insh[512 + 256 + j] = isd ? __float2half(sd_tab[isd * 128 + j]) : __half(0.f);
    }
    __syncthreads();

    const uint2* xq = reinterpret_cast<const uint2*>(qqh);   // [2][32]
    const uint2* xi = reinterpret_cast<const uint2*>(insh);  // [2][128]
    const uint2* xc = reinterpret_cast<const uint2*>(xch);   // [2][64]

    for (int s = 0; s < SS; s++) {
        // ---- Phase B: y2/y3 partials (fp16 weights, K=128 split 2-way) ----
        {
            const uint2* W = (g < 2) ? W2s : W3s;
            int kb = (g & 1) * 16;
            __half2 a0e = bits2h(0u), a0o = a0e, a1e = a0e, a1o = a0e;
            #pragma unroll
            for (int k4 = 0; k4 < 16; k4++) {
                uint2 w = W[(kb + k4) * 128 + j];
                __half2 wa = bits2h(w.x), wb = bits2h(w.y);
                uint2 x0 = xq[kb + k4];
                uint2 x1 = xq[32 + kb + k4];
                a0e = __hfma2(wa, bits2h(x0.x), a0e); a0o = __hfma2(wb, bits2h(x0.y), a0o);
                a1e = __hfma2(wa, bits2h(x1.x), a1e); a1o = __hfma2(wb, bits2h(x1.y), a1o);
            }
            pB[(g * 2 + 0) * 128 + j] = hsum4(a0e, a0o);
            pB[(g * 2 + 1) * 128 + j] = hsum4(a1e, a1o);
        }
        // ---- Phase E: y6 partials (fp8 W6, K=512 split 4-way) — independent of B ----
        {
            int kb = g * 32;
            __half2 a0e = bits2h(0u), a0o = a0e, a1e = a0e, a1o = a0e;
            #pragma unroll 8
            for (int k4 = 0; k4 < 32; k4++) {
                unsigned w = W6s[(kb + k4) * 128 + j];
                __half2 wa = cvt_e4m3x2((unsigned short)w);
                __half2 wb = cvt_e4m3x2((unsigned short)(w >> 16));
                uint2 x0 = xi[kb + k4];
                uint2 x1 = xi[128 + kb + k4];
                a0e = __hfma2(wa, bits2h(x0.x), a0e); a0o = __hfma2(wb, bits2h(x0.y), a0o);
                a1e = __hfma2(wa, bits2h(x1.x), a1e); a1o = __hfma2(wb, bits2h(x1.y), a1o);
            }
            pE[(g * 2 + 0) * 128 + j] = hsum4(a0e, a0o);
            pE[(g * 2 + 1) * 128 + j] = hsum4(a1e, a1o);
        }
        __syncthreads();

        // ---- combine B: sdft half of xcat ----
        if (g < 2) {
            int r = g;
            float y2 = pB[(0 * 2 + r) * 128 + j] + pB[(1 * 2 + r) * 128 + j] + b2j;
            float y3 = pB[(2 * 2 + r) * 128 + j] + pB[(3 * 2 + r) * 128 + j] + b3j;
            xch[r * 256 + j] = __float2half(sigm(y2) * tanh_f(y3));
        }
        __syncthreads();

        // ---- Phase D: y4/y5 partials (fp8, K=256 split 2-way each) ----
        {
            const unsigned* W = (g < 2) ? W4s : W5s;
            int kb = (g & 1) * 32;
            __half2 a0e = bits2h(0u), a0o = a0e, a1e = a0e, a1o = a0e;
            #pragma unroll 8
            for (int k4 = 0; k4 < 32; k4++) {
                unsigned w = W[(kb + k4) * 128 + j];
                __half2 wa = cvt_e4m3x2((unsigned short)w);
                __half2 wb = cvt_e4m3x2((unsigned short)(w >> 16));
                uint2 x0 = xc[kb + k4];
                uint2 x1 = xc[64 + kb + k4];
                a0e = __hfma2(wa, bits2h(x0.x), a0e); a0o = __hfma2(wb, bits2h(x0.y), a0o);
                a1e = __hfma2(wa, bits2h(x1.x), a1e); a1o = __hfma2(wb, bits2h(x1.y), a1o);
            }
            pB[(g * 2 + 0) * 128 + j] = hsum4(a0e, a0o);   // pB reused as pD
            pB[(g * 2 + 1) * 128 + j] = hsum4(a1e, a1o);
        }
        __syncthreads();

        // ---- final: k update (g0,g1) + next-step gathers (g2,g3) ----
        int sn = (s + 1 < SS) ? s + 1 : 0;
        if (g < 2) {
            int r = g, b = b0 + r;
            float y4 = (pB[(0 * 2 + r) * 128 + j] + pB[(1 * 2 + r) * 128 + j]) * W_INV + b4j;
            float y5 = (pB[(2 * 2 + r) * 128 + j] + pB[(3 * 2 + r) * 128 + j]) * W_INV + b5j;
            float pka = sigm(y4) * tanh_f(y5);
            float y6 = (pE[(0 * 2 + r) * 128 + j] + pE[(1 * 2 + r) * 128 + j]
                      + pE[(2 * 2 + r) * 128 + j] + pE[(3 * 2 + r) * 128 + j]) * W_INV + b6j;
            float g6 = sigm(y6);
            float kv = k_s[r * 128 + j];
            float kn = g6 * kv + (1.0f - g6) * pka;
            k_s[r * 128 + j] = kn;
            float inp = __half2float(g_inp[(sn * BB + b) * EE + j]);
            qqh[r * 128 + j]  = __float2half(kn - inp);
            insh[r * 512 + j] = __float2half(kn);
        } else if (g == 2) {
            #pragma unroll
            for (int r = 0; r < 2; r++) {
                int b = b0 + r;
                int ia = a[b * SS + sn];
                __half av = __float2half(a_tab[ia * 128 + j]);
                insh[r * 512 + 128 + j] = av;
                xch[r * 256 + 128 + j]  = av;
            }
            int isd = sd[b0 * SS + sn];
            insh[256 + j] = isd ? __float2half(sd_tab[isd * 128 + j]) : __half(0.f);
        } else {
            #pragma unroll
            for (int r = 0; r < 2; r++) {
                int b = b0 + r;
                int iq = qd[b * SS + sn];
                insh[r * 512 + 384 + j] = iq ? __float2half(qd_tab[iq * 128 + j]) : __half(0.f);
            }
            int isd = sd[(b0 + 1) * SS + sn];
            insh[512 + 256 + j] = isd ? __float2half(sd_tab[isd * 128 + j]) : __half(0.f);
        }
        __syncthreads();
    }

    if (g < 2) {
        out[(b0 + g) * EE + j] = sigm(k_s[g * 128 + j]);
    }
}

// ---------------- launch ----------------
extern "C" void kernel_launch(void* const* d_in, const int* in_sizes, int n_in,
                              void* d_out, int out_size) {
    (void)in_sizes; (void)n_in; (void)out_size;
    const int*   c        = (const int*)d_in[1];
    const int*   sd       = (const int*)d_in[2];
    const int*   qd       = (const int*)d_in[3];
    const int*   a        = (const int*)d_in[4];
    const float* qemb     = (const float*)d_in[9];
    const float* c_tab    = (const float*)d_in[10];
    const float* sd_tab   = (const float*)d_in[11];
    const float* qd_tab   = (const float*)d_in[12];
    const float* a_tab    = (const float*)d_in[13];
    const float* know     = (const float*)d_in[14];
    const float* W1       = (const float*)d_in[15];
    const float* b1       = (const float*)d_in[16];
    const float* W2       = (const float*)d_in[17];
    const float* b2       = (const float*)d_in[18];
    const float* W3       = (const float*)d_in[19];
    const float* b3       = (const float*)d_in[20];
    const float* W4       = (const float*)d_in[21];
    const float* b4       = (const float*)d_in[22];
    const float* W5       = (const float*)d_in[23];
    const float* b5       = (const float*)d_in[24];
    const float* W6       = (const float*)d_in[25];
    const float* b6       = (const float*)d_in[26];
    float* out = (float*)d_out;

    cudaFuncSetAttribute(k_scan, cudaFuncAttributeMaxDynamicSharedMemorySize, SM_TOTAL);

    prep_all<<<224, 256>>>(W1, W2, W3, W4, W5, W6);
    k_input<<<8000, 256>>>(qemb, c, sd, qd, c_tab, sd_tab, qd_tab, b1);
    k_scan<<<128, 512, SM_TOTAL>>>(a, sd, qd, sd_tab, qd_tab, a_tab, know,
                                   b2, b3, b4, b5, b6, out);
}

// round 14
// speedup vs baseline: 1.9199x; 1.0664x over previous
#include <cuda_runtime.h>
#include <cuda_fp16.h>

#define BB 256
#define SS 500
#define EE 128

// ---------------- device-global scratch ----------------
__device__ __half   g_inp[SS * BB * EE];   // linear1 out, time-major [s][b][e], fp16 (16.4M halves)
__device__ uint2    g_W1f[16 * 32 * 32];   // W1 in mma B-fragment order [ntile][ktile][lane]
__device__ uint2    g_W2h[32 * 128];       // fp16x4 [k4][j]
__device__ uint2    g_W3h[32 * 128];
__device__ unsigned g_W4q[64 * 128];       // e4m3x4 (x64 scale) [k4][j]
__device__ unsigned g_W5q[64 * 128];
__device__ unsigned g_W6q[128 * 128];

#define W_SCALE 64.0f
#define W_INV   (1.0f / 64.0f)

// ---------------- helpers ----------------
__device__ __forceinline__ float sigm(float x)   { return 1.0f / (1.0f + __expf(-x)); }
__device__ __forceinline__ float tanh_f(float x) { return 1.0f - 2.0f / (__expf(2.0f * x) + 1.0f); }
__device__ __forceinline__ __half2 cvt_e4m3x2(unsigned short v) {
    unsigned r;
    asm("cvt.rn.f16x2.e4m3x2 %0, %1;" : "=r"(r) : "h"(v));
    return *reinterpret_cast<__half2*>(&r);
}
__device__ __forceinline__ unsigned short pack_e4m3x2(float lo, float hi) {
    unsigned short r;
    asm("cvt.rn.satfinite.e4m3x2.f32 %0, %1, %2;" : "=h"(r) : "f"(hi), "f"(lo));
    return r;
}
__device__ __forceinline__ unsigned h2bits(__half2 h) { return *reinterpret_cast<unsigned*>(&h); }
__device__ __forceinline__ __half2 bits2h(unsigned v) { return *reinterpret_cast<__half2*>(&v); }
__device__ __forceinline__ float2 f2sum(__half2 a, __half2 b, __half2 c, __half2 d) {
    float2 fa = __half22float2(a), fb = __half22float2(b);
    float2 fc = __half22float2(c), fd = __half22float2(d);
    float2 r; r.x = (fa.x + fb.x) + (fc.x + fd.x); r.y = (fa.y + fb.y) + (fc.y + fd.y);
    return r;
}

// ---------------- prep: pack all weights ----------------
__global__ void prep_all(const float* __restrict__ W1, const float* __restrict__ W2,
                         const float* __restrict__ W3, const float* __restrict__ W4,
                         const float* __restrict__ W5, const float* __restrict__ W6) {
    int t = blockIdx.x * blockDim.x + threadIdx.x;
    if (t < 16384) {
        // W1 -> mma m16n8k16 B fragments (col-major B = W1[n][k] natural layout)
        int lane = t & 31, kt = (t >> 5) & 31, nt = t >> 10;
        int n  = nt * 8 + (lane >> 2);
        int k0 = kt * 16 + (lane & 3) * 2;
        const float* s = W1 + n * 512 + k0;
        uint2 v;
        v.x = h2bits(__floats2half2_rn(s[0], s[1]));
        v.y = h2bits(__floats2half2_rn(s[8], s[9]));
        g_W1f[t] = v;
    } else if (t < 24576) {
        int o = t - 16384;
        const float* W = (o < 4096) ? W2 : W3;
        uint2* dst = (o < 4096) ? g_W2h : g_W3h;
        o &= 4095;
        int k4 = o >> 7, j = o & 127;
        const float* s = W + j * 128 + k4 * 4;
        uint2 v;
        v.x = h2bits(__floats2half2_rn(s[0], s[1]));
        v.y = h2bits(__floats2half2_rn(s[2], s[3]));
        dst[o] = v;
    } else if (t < 57344) {
        int o = t - 24576;
        const float* W; unsigned* dst; int in_dim;
        if (o < 8192)        { W = W4; dst = g_W4q; in_dim = 256; }
        else if (o < 16384)  { o -= 8192;  W = W5; dst = g_W5q; in_dim = 256; }
        else                 { o -= 16384; W = W6; dst = g_W6q; in_dim = 512; }
        int k4 = o >> 7, j = o & 127;
        const float* s = W + j * in_dim + k4 * 4;
        unsigned lo = pack_e4m3x2(s[0] * W_SCALE, s[1] * W_SCALE);
        unsigned hi = pack_e4m3x2(s[2] * W_SCALE, s[3] * W_SCALE);
        dst[o] = lo | (hi << 16);
    }
}

// ---------------- kernel 1: input GEMM via mma.sync m16n8k16 ----------------
// 64 rows/CTA, 256 threads (8 warps). Warp w: ntiles {2w, 2w+1}, all 4 mtiles.
// x-tile fp16 in smem, XOR-swizzled for conflict-free ldmatrix.
__global__ void __launch_bounds__(256) k_input(
    const float* __restrict__ qemb, const int* __restrict__ c,
    const int* __restrict__ sd, const int* __restrict__ qd,
    const float* __restrict__ c_tab, const float* __restrict__ sd_tab,
    const float* __restrict__ qd_tab, const float* __restrict__ b1)
{
    extern __shared__ char smem[];          // 64KB: 64 rows x 512 halves, swizzled
    __shared__ int sidx[64][3];
    int tid = threadIdx.x;
    int row0 = blockIdx.x * 64;

    if (tid < 192) {
        int rr = tid / 3, w = tid % 3;
        int row = row0 + rr;
        sidx[rr][w] = (w == 0) ? c[row] : ((w == 1) ? sd[row] : qd[row]);
    }
    __syncthreads();

    // gather: 4096 16B chunks (8 halves each); chunk ch of row r at slot (ch ^ (r&7))
    uint4* xs4 = reinterpret_cast<uint4*>(smem);
    #pragma unroll
    for (int i = 0; i < 16; i++) {
        int cl = tid + i * 256;          // 0..4095
        int r = cl >> 6, ch = cl & 63;
        int seg = ch >> 4, f8 = ch & 15; // f8 = 8-float group within 128-elem segment
        float4 v0, v1;
        if (seg == 0) {
            const float4* src = reinterpret_cast<const float4*>(qemb) + (row0 + r) * 32 + f8 * 2;
            v0 = src[0]; v1 = src[1];
        } else {
            int idx = sidx[r][seg - 1];
            const float* tab = (seg == 1) ? c_tab : (seg == 2) ? sd_tab : qd_tab;
            const float4* src = reinterpret_cast<const float4*>(tab) + idx * 32 + f8 * 2;
            v0 = src[0]; v1 = src[1];
            if (idx == 0) { v0 = make_float4(0,0,0,0); v1 = make_float4(0,0,0,0); }
        }
        uint4 p;
        p.x = h2bits(__floats2half2_rn(v0.x, v0.y));
        p.y = h2bits(__floats2half2_rn(v0.z, v0.w));
        p.z = h2bits(__floats2half2_rn(v1.x, v1.y));
        p.w = h2bits(__floats2half2_rn(v1.z, v1.w));
        xs4[r * 64 + (ch ^ (r & 7))] = p;
    }
    __syncthreads();

    int w = tid >> 5, lane = tid & 31;
    int n0 = 2 * w;                       // first of 2 ntiles
    int lhalf = lane >> 4;                // k-half for ldmatrix
    unsigned smem_u32 = (unsigned)__cvta_generic_to_shared(smem);
    unsigned rowbase = smem_u32 + (unsigned)((lane & 15) * 1024);

    float acc0[4][4], acc1[4][4];
    #pragma unroll
    for (int mt = 0; mt < 4; mt++)
        #pragma unroll
        for (int i = 0; i < 4; i++) { acc0[mt][i] = 0.f; acc1[mt][i] = 0.f; }

    const uint2* B0 = g_W1f + (n0 * 32) * 32 + lane;
    const uint2* B1 = B0 + 32 * 32;

    #pragma unroll 4
    for (int kt = 0; kt < 32; kt++) {
        unsigned swoff = (unsigned)((((2 * kt + lhalf) ^ (lane & 7)) << 4));
        unsigned a[4][4];
        #pragma unroll
        for (int mt = 0; mt < 4; mt++) {
            unsigned addr = rowbase + (unsigned)(mt * 16384) + swoff;
            asm volatile("ldmatrix.sync.aligned.m8n8.x4.shared.b16 {%0,%1,%2,%3}, [%4];"
                : "=r"(a[mt][0]), "=r"(a[mt][1]), "=r"(a[mt][2]), "=r"(a[mt][3]) : "r"(addr));
        }
        uint2 bw0 = __ldg(B0 + kt * 32);
        uint2 bw1 = __ldg(B1 + kt * 32);
        #pragma unroll
        for (int mt = 0; mt < 4; mt++) {
            asm volatile("mma.sync.aligned.m16n8k16.row.col.f32.f16.f16.f32 "
                "{%0,%1,%2,%3}, {%4,%5,%6,%7}, {%8,%9}, {%0,%1,%2,%3};"
                : "+f"(acc0[mt][0]), "+f"(acc0[mt][1]), "+f"(acc0[mt][2]), "+f"(acc0[mt][3])
                : "r"(a[mt][0]), "r"(a[mt][1]), "r"(a[mt][2]), "r"(a[mt][3]),
                  "r"(bw0.x), "r"(bw0.y));
            asm volatile("mma.sync.aligned.m16n8k16.row.col.f32.f16.f16.f32 "
                "{%0,%1,%2,%3}, {%4,%5,%6,%7}, {%8,%9}, {%0,%1,%2,%3};"
                : "+f"(acc1[mt][0]), "+f"(acc1[mt][1]), "+f"(acc1[mt][2]), "+f"(acc1[mt][3])
                : "r"(a[mt][0]), "r"(a[mt][1]), "r"(a[mt][2]), "r"(a[mt][3]),
                  "r"(bw1.x), "r"(bw1.y));
        }
    }

    // epilogue: add bias, convert to half2, scatter to g_inp[(s*BB+b)*EE+j]
    int jb0 = n0 * 8 + (lane & 3) * 2;
    int jb1 = jb0 + 8;
    float2 bias0 = *reinterpret_cast<const float2*>(b1 + jb0);
    float2 bias1 = *reinterpret_cast<const float2*>(b1 + jb1);
    #pragma unroll
    for (int mt = 0; mt < 4; mt++) {
        int R0 = row0 + mt * 16 + (lane >> 2);
        int R1 = R0 + 8;
        int bb0 = R0 / SS, ss0 = R0 - bb0 * SS;
        int bb1 = R1 / SS, ss1 = R1 - bb1 * SS;
        int base0 = (ss0 * BB + bb0) * EE;
        int base1 = (ss1 * BB + bb1) * EE;
        *reinterpret_cast<__half2*>(&g_inp[base0 + jb0]) =
            __floats2half2_rn(acc0[mt][0] + bias0.x, acc0[mt][1] + bias0.y);
        *reinterpret_cast<__half2*>(&g_inp[base1 + jb0]) =
            __floats2half2_rn(acc0[mt][2] + bias0.x, acc0[mt][3] + bias0.y);
        *reinterpret_cast<__half2*>(&g_inp[base0 + jb1]) =
            __floats2half2_rn(acc1[mt][0] + bias1.x, acc1[mt][1] + bias1.y);
        *reinterpret_cast<__half2*>(&g_inp[base1 + jb1]) =
            __floats2half2_rn(acc1[mt][2] + bias1.x, acc1[mt][3] + bias1.y);
    }
}

// ---------------- scan kernel ----------------
// 512 threads: (j in [0,128), group g in {0..3}); 2 batch rows/CTA, row-interleaved half2.
#define SO_W2   0
#define SO_W3   32768
#define SO_W4   65536
#define SO_W5   98304
#define SO_W6   131072
#define SO_KS   196608
#define SO_QQ   197632
#define SO_INS  198144
#define SO_XC   200192
#define SO_PB   201216
#define SO_PE   205312
#define SM_TOTAL 209408

__global__ void __launch_bounds__(512, 1) k_scan(
    const int* __restrict__ a, const int* __restrict__ sd, const int* __restrict__ qd,
    const float* __restrict__ sd_tab, const float* __restrict__ qd_tab,
    const float* __restrict__ a_tab, const float* __restrict__ knowledge,
    const float* __restrict__ b2, const float* __restrict__ b3,
    const float* __restrict__ b4, const float* __restrict__ b5,
    const float* __restrict__ b6, float* __restrict__ out)
{
    extern __shared__ char sm[];
    uint2*    W2s = reinterpret_cast<uint2*>(sm + SO_W2);
    uint2*    W3s = reinterpret_cast<uint2*>(sm + SO_W3);
    unsigned* W4s = reinterpret_cast<unsigned*>(sm + SO_W4);
    unsigned* W5s = reinterpret_cast<unsigned*>(sm + SO_W5);
    unsigned* W6s = reinterpret_cast<unsigned*>(sm + SO_W6);
    float2*   k_s = reinterpret_cast<float2*>(sm + SO_KS);    // [128] (r0,r1)
    __half2*  qq2 = reinterpret_cast<__half2*>(sm + SO_QQ);   // [128]
    __half2*  in2 = reinterpret_cast<__half2*>(sm + SO_INS);  // [512]
    __half2*  xc2 = reinterpret_cast<__half2*>(sm + SO_XC);   // [256]
    float2*   pB  = reinterpret_cast<float2*>(sm + SO_PB);    // [4][128] (reused as pD)
    float2*   pE  = reinterpret_cast<float2*>(sm + SO_PE);    // [4][128]

    const uint4* xq4 = reinterpret_cast<const uint4*>(sm + SO_QQ);   // [32]
    const uint4* xi4 = reinterpret_cast<const uint4*>(sm + SO_INS);  // [128]
    const uint4* xc4 = reinterpret_cast<const uint4*>(sm + SO_XC);   // [64]

    int tid = threadIdx.x;
    int j = tid & 127, g = tid >> 7;
    int b0 = blockIdx.x * 2;

    for (int i = tid; i < 4096;  i += 512) { W2s[i] = g_W2h[i]; W3s[i] = g_W3h[i]; }
    for (int i = tid; i < 8192;  i += 512) { W4s[i] = g_W4q[i]; W5s[i] = g_W5q[i]; }
    for (int i = tid; i < 16384; i += 512) { W6s[i] = g_W6q[i]; }

    float b2j = b2[j], b3j = b3[j], b4j = b4[j], b5j = b5[j], b6j = b6[j];

    // init (s = 0)
    if (g == 0) {
        float kv = knowledge[j];
        k_s[j] = make_float2(kv, kv);
        float i0 = __half2float(g_inp[(0 * BB + b0) * EE + j]);
        float i1 = __half2float(g_inp[(0 * BB + b0 + 1) * EE + j]);
        qq2[j] = __floats2half2_rn(kv - i0, kv - i1);
        in2[j] = __floats2half2_rn(kv, kv);
    } else if (g == 1) {
        int ia0 = a[b0 * SS], ia1 = a[(b0 + 1) * SS];
        __half2 av = __floats2half2_rn(a_tab[ia0 * 128 + j], a_tab[ia1 * 128 + j]);
        in2[128 + j] = av; xc2[128 + j] = av;
    } else if (g == 2) {
        int i0 = sd[b0 * SS], i1 = sd[(b0 + 1) * SS];
        in2[256 + j] = __floats2half2_rn(i0 ? sd_tab[i0 * 128 + j] : 0.f,
                                         i1 ? sd_tab[i1 * 128 + j] : 0.f);
    } else {
        int i0 = qd[b0 * SS], i1 = qd[(b0 + 1) * SS];
        in2[384 + j] = __floats2half2_rn(i0 ? qd_tab[i0 * 128 + j] : 0.f,
                                         i1 ? qd_tab[i1 * 128 + j] : 0.f);
    }
    __syncthreads();

    float inpf0 = 0.f, inpf1 = 0.f;   // g0's prefetched next-step inputs

    for (int s = 0; s < SS; s++) {
        int sn = (s + 1 < SS) ? s + 1 : 0;

        // ---- Phase B+E ----
        {
            const uint2* W = (g < 2) ? W2s : W3s;
            int kb = (g & 1) * 16;
            __half2 z = bits2h(0u);
            __half2 aa = z, ab = z, ac = z, ad = z;
            #pragma unroll
            for (int k4 = 0; k4 < 16; k4++) {
                uint2 w = W[(kb + k4) * 128 + j];
                __half2 wa = bits2h(w.x), wb = bits2h(w.y);
                uint4 x = xq4[kb + k4];
                aa = __hfma2(__low2half2(wa),  bits2h(x.x), aa);
                ab = __hfma2(__high2half2(wa), bits2h(x.y), ab);
                ac = __hfma2(__low2half2(wb),  bits2h(x.z), ac);
                ad = __hfma2(__high2half2(wb), bits2h(x.w), ad);
            }
            pB[g * 128 + j] = f2sum(aa, ab, ac, ad);
        }
        {
            int kb = g * 32;
            __half2 z = bits2h(0u);
            __half2 aa = z, ab = z, ac = z, ad = z;
            #pragma unroll 8
            for (int k4 = 0; k4 < 32; k4++) {
                unsigned w = W6s[(kb + k4) * 128 + j];
                __half2 wa = cvt_e4m3x2((unsigned short)w);
                __half2 wb = cvt_e4m3x2((unsigned short)(w >> 16));
                uint4 x = xi4[kb + k4];
                aa = __hfma2(__low2half2(wa),  bits2h(x.x), aa);
                ab = __hfma2(__high2half2(wa), bits2h(x.y), ab);
                ac = __hfma2(__low2half2(wb),  bits2h(x.z), ac);
                ad = __hfma2(__high2half2(wb), bits2h(x.w), ad);
            }
            pE[g * 128 + j] = f2sum(aa, ab, ac, ad);
        }
        __syncthreads();

        // ---- combine: sdft -> xc2[0..127]; sd/qd gathers for next step; inp prefetch ----
        if (g == 0) {
            float2 p0 = pB[j], p1 = pB[128 + j], p2 = pB[256 + j], p3 = pB[384 + j];
            float y20 = p0.x + p1.x + b2j, y21 = p0.y + p1.y + b2j;
            float y30 = p2.x + p3.x + b3j, y31 = p2.y + p3.y + b3j;
            xc2[j] = __floats2half2_rn(sigm(y20) * tanh_f(y30), sigm(y21) * tanh_f(y31));
            inpf0 = __half2float(g_inp[(sn * BB + b0) * EE + j]);
            inpf1 = __half2float(g_inp[(sn * BB + b0 + 1) * EE + j]);
        } else if (g == 2) {
            int i0 = sd[b0 * SS + sn], i1 = sd[(b0 + 1) * SS + sn];
            in2[256 + j] = __floats2half2_rn(i0 ? sd_tab[i0 * 128 + j] : 0.f,
                                             i1 ? sd_tab[i1 * 128 + j] : 0.f);
        } else if (g == 3) {
            int i0 = qd[b0 * SS + sn], i1 = qd[(b0 + 1) * SS + sn];
            in2[384 + j] = __floats2half2_rn(i0 ? qd_tab[i0 * 128 + j] : 0.f,
                                             i1 ? qd_tab[i1 * 128 + j] : 0.f);
        }
        __syncthreads();

        // ---- Phase D: y4 (g0,g1) / y5 (g2,g3), K=256 ----
        {
            const unsigned* W = (g < 2) ? W4s : W5s;
            int kb = (g & 1) * 32;
            __half2 z = bits2h(0u);
            __half2 aa = z, ab = z, ac = z, ad = z;
            #pragma unroll 8
            for (int k4 = 0; k4 < 32; k4++) {
                unsigned w = W[(kb + k4) * 128 + j];
                __half2 wa = cvt_e4m3x2((unsigned short)w);
                __half2 wb = cvt_e4m3x2((unsigned short)(w >> 16));
                uint4 x = xc4[kb + k4];
                aa = __hfma2(__low2half2(wa),  bits2h(x.x), aa);
                ab = __hfma2(__high2half2(wa), bits2h(x.y), ab);
                ac = __hfma2(__low2half2(wb),  bits2h(x.z), ac);
                ad = __hfma2(__high2half2(wb), bits2h(x.w), ad);
            }
            pB[g * 128 + j] = f2sum(aa, ab, ac, ad);   // pD
        }
        __syncthreads();

        // ---- final: k update (g0) + a_e gather (g1) ----
        if (g == 0) {
            float2 d0 = pB[j], d1 = pB[128 + j], d2 = pB[256 + j], d3 = pB[384 + j];
            float2 e0 = pE[j], e1 = pE[128 + j], e2 = pE[256 + j], e3 = pE[384 + j];
            float y40 = (d0.x + d1.x) * W_INV + b4j, y41 = (d0.y + d1.y) * W_INV + b4j;
            float y50 = (d2.x + d3.x) * W_INV + b5j, y51 = (d2.y + d3.y) * W_INV + b5j;
            float y60 = ((e0.x + e1.x) + (e2.x + e3.x)) * W_INV + b6j;
            float y61 = ((e0.y + e1.y) + (e2.y + e3.y)) * W_INV + b6j;
            float pk0 = sigm(y40) * tanh_f(y50);
            float pk1 = sigm(y41) * tanh_f(y51);
            float g60 = sigm(y60), g61 = sigm(y61);
            float2 kv = k_s[j];
            float kn0 = g60 * kv.x + (1.0f - g60) * pk0;
            float kn1 = g61 * kv.y + (1.0f - g61) * pk1;
            k_s[j] = make_float2(kn0, kn1);
            qq2[j] = __floats2half2_rn(kn0 - inpf0, kn1 - inpf1);
            in2[j] = __floats2half2_rn(kn0, kn1);
        } else if (g == 1) {
            int ia0 = a[b0 * SS + sn], ia1 = a[(b0 + 1) * SS + sn];
            __half2 av = __floats2half2_rn(a_tab[ia0 * 128 + j], a_tab[ia1 * 128 + j]);
            in2[128 + j] = av; xc2[128 + j] = av;
        }
        __syncthreads();
    }

    if (g == 0) {
        float2 kv = k_s[j];
        out[b0 * EE + j]       = sigm(kv.x);
        out[(b0 + 1) * EE + j] = sigm(kv.y);
    }
}

// ---------------- launch ----------------
extern "C" void kernel_launch(void* const* d_in, const int* in_sizes, int n_in,
                              void* d_out, int out_size) {
    (void)in_sizes; (void)n_in; (void)out_size;
    const int*   c        = (const int*)d_in[1];
    const int*   sd       = (const int*)d_in[2];
    const int*   qd       = (const int*)d_in[3];
    const int*   a        = (const int*)d_in[4];
    const float* qemb     = (const float*)d_in[9];
    const float* c_tab    = (const float*)d_in[10];
    const float* sd_tab   = (const float*)d_in[11];
    const float* qd_tab   = (const float*)d_in[12];
    const float* a_tab    = (const float*)d_in[13];
    const float* know     = (const float*)d_in[14];
    const float* W1       = (const float*)d_in[15];
    const float* b1       = (const float*)d_in[16];
    const float* W2       = (const float*)d_in[17];
    const float* b2       = (const float*)d_in[18];
    const float* W3       = (const float*)d_in[19];
    const float* b3       = (const float*)d_in[20];
    const float* W4       = (const float*)d_in[21];
    const float* b4       = (const float*)d_in[22];
    const float* W5       = (const float*)d_in[23];
    const float* b5       = (const float*)d_in[24];
    const float* W6       = (const float*)d_in[25];
    const float* b6       = (const float*)d_in[26];
    float* out = (float*)d_out;

    cudaFuncSetAttribute(k_scan,  cudaFuncAttributeMaxDynamicSharedMemorySize, SM_TOTAL);
    cudaFuncSetAttribute(k_input, cudaFuncAttributeMaxDynamicSharedMemorySize, 65536);

    prep_all<<<224, 256>>>(W1, W2, W3, W4, W5, W6);
    k_input<<<2000, 256, 65536>>>(qemb, c, sd, qd, c_tab, sd_tab, qd_tab, b1);
    k_scan<<<128, 512, SM_TOTAL>>>(a, sd, qd, sd_tab, qd_tab, a_tab, know,
                                   b2, b3, b4, b5, b6, out);
}

// round 17
// speedup vs baseline: 2.7218x; 1.4177x over previous
#include <cuda_runtime.h>
#include <cuda_fp16.h>

#define BB 256
#define SS 500
#define EE 128

// ---------------- device-global scratch ----------------
__device__ __half g_P2[SS * BB * EE];     // (W2W1)x + W2b1 - b2, time-major [s][b][j]
__device__ __half g_P3[SS * BB * EE];
__device__ __half g_B6[SS * BB * EE];     // W6[:,128:512]@[a_e,sd_e,qd_e] + b6
__device__ float  g_W21[128 * 512];       // W2@W1
__device__ float  g_W31[128 * 512];
__device__ float  g_bP[384];              // GEMM epilogue bias (0 for B6 part)
__device__ float  g_lut4a[2 * 128];       // W4[:,128:]@a_tab[i] + b4
__device__ float  g_lut5a[2 * 128];
__device__ float  g_lut6a[2 * 128];       // W6[:,128:256]@a_tab[i] + b6
__device__ uint2  g_WPf[48 * 32 * 32];    // fused GEMM B-fragments [ntile][ktile][lane]
__device__ uint2  g_W2h[32 * 128];        // scan weights fp16x4 [k4][j]
__device__ uint2  g_W3h[32 * 128];
__device__ uint2  g_W4sh[32 * 128];       // W4 sdft cols (0..127)
__device__ uint2  g_W5sh[32 * 128];
__device__ uint2  g_W6kh[32 * 128];       // W6 k cols (0..127)

// ---------------- helpers ----------------
__device__ __forceinline__ float sigm(float x)   { return 1.0f / (1.0f + __expf(-x)); }
__device__ __forceinline__ float tanh_f(float x) { return 1.0f - 2.0f / (__expf(2.0f * x) + 1.0f); }
__device__ __forceinline__ unsigned h2bits(__half2 h) { return *reinterpret_cast<unsigned*>(&h); }
__device__ __forceinline__ __half2 bits2h(unsigned v) { return *reinterpret_cast<__half2*>(&v); }
__device__ __forceinline__ float2 f2sum(__half2 a, __half2 b, __half2 c, __half2 d) {
    float2 fa = __half22float2(a), fb = __half22float2(b);
    float2 fc = __half22float2(c), fd = __half22float2(d);
    float2 r; r.x = (fa.x + fb.x) + (fc.x + fd.x); r.y = (fa.y + fb.y) + (fc.y + fd.y);
    return r;
}

// ---------------- prep1: fused weights, luts, biases, scan packs ----------------
__global__ void prep1(const float* __restrict__ W1, const float* __restrict__ W2,
                      const float* __restrict__ W3, const float* __restrict__ W4,
                      const float* __restrict__ W5, const float* __restrict__ W6,
                      const float* __restrict__ b1, const float* __restrict__ b2,
                      const float* __restrict__ b3, const float* __restrict__ b4,
                      const float* __restrict__ b5, const float* __restrict__ b6,
                      const float* __restrict__ a_tab) {
    int t = blockIdx.x * blockDim.x + threadIdx.x;
    if (t < 131072) {
        // W21 / W31 = W{2,3} @ W1 : [128][512]
        const float* Wf = (t < 65536) ? W2 : W3;
        float* dst = (t < 65536) ? g_W21 : g_W31;
        int o = t & 65535;
        int n = o >> 9, k = o & 511;
        float s = 0.f;
        #pragma unroll 4
        for (int m = 0; m < 128; m++) s += Wf[n * 128 + m] * W1[m * 512 + k];
        dst[o] = s;
    } else if (t < 131456) {
        int n = t - 131072;   // 0..383
        float s = 0.f;
        if (n < 128) {
            #pragma unroll 4
            for (int m = 0; m < 128; m++) s += W2[n * 128 + m] * b1[m];
            s -= b2[n];
        } else if (n < 256) {
            int nn = n - 128;
            #pragma unroll 4
            for (int m = 0; m < 128; m++) s += W3[nn * 128 + m] * b1[m];
            s -= b3[nn];
        }
        g_bP[n] = s;
    } else if (t < 132224) {
        int o = t - 131456;          // 0..767
        int which = o >> 8;          // 0:lut4a 1:lut5a 2:lut6a
        int u = o & 255;
        int i = u >> 7, j = u & 127;
        const float* W = (which == 0) ? W4 : (which == 1) ? W5 : W6;
        int in_dim = (which == 2) ? 512 : 256;
        float s = 0.f;
        #pragma unroll 4
        for (int m = 0; m < 128; m++) s += W[j * in_dim + 128 + m] * a_tab[i * 128 + m];
        s += (which == 0) ? b4[j] : (which == 1) ? b5[j] : b6[j];
        float* dst = (which == 0) ? g_lut4a : (which == 1) ? g_lut5a : g_lut6a;
        dst[u] = s;
    } else if (t < 152704) {
        int o = t - 132224;          // 0..20479
        int arr = o >> 12, q = o & 4095;
        int k4 = q >> 7, j = q & 127;
        const float* s;
        uint2* dst;
        switch (arr) {
            case 0: s = W2 + j * 128 + k4 * 4; dst = g_W2h; break;
            case 1: s = W3 + j * 128 + k4 * 4; dst = g_W3h; break;
            case 2: s = W4 + j * 256 + k4 * 4; dst = g_W4sh; break;
            case 3: s = W5 + j * 256 + k4 * 4; dst = g_W5sh; break;
            default: s = W6 + j * 512 + k4 * 4; dst = g_W6kh; break;
        }
        uint2 v;
        v.x = h2bits(__floats2half2_rn(s[0], s[1]));
        v.y = h2bits(__floats2half2_rn(s[2], s[3]));
        dst[q] = v;
    }
}

// ---------------- prep2: pack fused GEMM weights into mma B-fragments ----------------
// N=384: rows 0..127 = W21, 128..255 = W31, 256..383 = W6 (k-cols zeroed)
__global__ void prep2(const float* __restrict__ W6) {
    int t = blockIdx.x * blockDim.x + threadIdx.x;
    if (t >= 49152) return;
    int lane = t & 31, kt = (t >> 5) & 31, nt = t >> 10;
    int n  = nt * 8 + (lane >> 2);
    int k0 = kt * 16 + (lane & 3) * 2;
    float v0, v1, v2, v3;
    if (n < 128) {
        const float* M = g_W21 + n * 512;
        v0 = M[k0]; v1 = M[k0 + 1]; v2 = M[k0 + 8]; v3 = M[k0 + 9];
    } else if (n < 256) {
        const float* M = g_W31 + (n - 128) * 512;
        v0 = M[k0]; v1 = M[k0 + 1]; v2 = M[k0 + 8]; v3 = M[k0 + 9];
    } else {
        if (k0 < 256) { v0 = v1 = v2 = v3 = 0.f; }
        else {
            const float* M = W6 + (n - 256) * 512;
            v0 = M[k0]; v1 = M[k0 + 1]; v2 = M[k0 + 8]; v3 = M[k0 + 9];
        }
    }
    uint2 v;
    v.x = h2bits(__floats2half2_rn(v0, v1));
    v.y = h2bits(__floats2half2_rn(v2, v3));
    g_WPf[t] = v;
}

// ---------------- fused input GEMM: [P2|P3|B6] = X @ [W21|W31|W6x]^T + bias ----------------
// 64 rows/CTA, 256 threads (8 warps). Warp w: ntiles w*6..w*6+5, all 4 mtiles.
__global__ void __launch_bounds__(256) k_inputP(
    const float* __restrict__ qemb, const int* __restrict__ c,
    const int* __restrict__ sd, const int* __restrict__ qd,
    const float* __restrict__ c_tab, const float* __restrict__ sd_tab,
    const float* __restrict__ qd_tab, const int* __restrict__ a)
{
    extern __shared__ char smem[];          // 64KB: 64 rows x 512 halves, swizzled
    __shared__ int sidx[64][3];
    int tid = threadIdx.x;
    int row0 = blockIdx.x * 64;

    if (tid < 192) {
        int rr = tid / 3, wsel = tid % 3;
        int row = row0 + rr;
        sidx[rr][wsel] = (wsel == 0) ? c[row] : ((wsel == 1) ? sd[row] : qd[row]);
    }
    __syncthreads();

    uint4* xs4 = reinterpret_cast<uint4*>(smem);
    #pragma unroll
    for (int i = 0; i < 16; i++) {
        int cl = tid + i * 256;          // 0..4095
        int r = cl >> 6, ch = cl & 63;
        int seg = ch >> 4, f8 = ch & 15;
        float4 v0, v1;
        if (seg == 0) {
            const float4* src = reinterpret_cast<const float4*>(qemb) + (row0 + r) * 32 + f8 * 2;
            v0 = src[0]; v1 = src[1];
        } else {
            int idx = sidx[r][seg - 1];
            const float* tab = (seg == 1) ? c_tab : (seg == 2) ? sd_tab : qd_tab;
            const float4* src = reinterpret_cast<const float4*>(tab) + idx * 32 + f8 * 2;
            v0 = src[0]; v1 = src[1];
            if (idx == 0) { v0 = make_float4(0,0,0,0); v1 = make_float4(0,0,0,0); }
        }
        uint4 p;
        p.x = h2bits(__floats2half2_rn(v0.x, v0.y));
        p.y = h2bits(__floats2half2_rn(v0.z, v0.w));
        p.z = h2bits(__floats2half2_rn(v1.x, v1.y));
        p.w = h2bits(__floats2half2_rn(v1.z, v1.w));
        xs4[r * 64 + (ch ^ (r & 7))] = p;
    }
    __syncthreads();

    int w = tid >> 5, lane = tid & 31;
    int lhalf = lane >> 4;
    unsigned smem_u32 = (unsigned)__cvta_generic_to_shared(smem);
    unsigned rowbase = smem_u32 + (unsigned)((lane & 15) * 1024);

    float acc[4][6][4];
    #pragma unroll
    for (int mt = 0; mt < 4; mt++)
        #pragma unroll
        for (int i = 0; i < 6; i++)
            #pragma unroll
            for (int q = 0; q < 4; q++) acc[mt][i][q] = 0.f;

    const uint2* Bp = g_WPf + (w * 6) * 32 * 32 + lane;

    #pragma unroll 2
    for (int kt = 0; kt < 32; kt++) {
        unsigned swoff = (unsigned)((((2 * kt + lhalf) ^ (lane & 7)) << 4));
        unsigned afr[4][4];
        #pragma unroll
        for (int mt = 0; mt < 4; mt++) {
            unsigned addr = rowbase + (unsigned)(mt * 16384) + swoff;
            asm volatile("ldmatrix.sync.aligned.m8n8.x4.shared.b16 {%0,%1,%2,%3}, [%4];"
                : "=r"(afr[mt][0]), "=r"(afr[mt][1]), "=r"(afr[mt][2]), "=r"(afr[mt][3]) : "r"(addr));
        }
        uint2 bw[6];
        #pragma unroll
        for (int i = 0; i < 6; i++) bw[i] = __ldg(Bp + i * 1024 + kt * 32);
        #pragma unroll
        for (int mt = 0; mt < 4; mt++)
            #pragma unroll
            for (int i = 0; i < 6; i++) {
                asm volatile("mma.sync.aligned.m16n8k16.row.col.f32.f16.f16.f32 "
                    "{%0,%1,%2,%3}, {%4,%5,%6,%7}, {%8,%9}, {%0,%1,%2,%3};"
                    : "+f"(acc[mt][i][0]), "+f"(acc[mt][i][1]), "+f"(acc[mt][i][2]), "+f"(acc[mt][i][3])
                    : "r"(afr[mt][0]), "r"(afr[mt][1]), "r"(afr[mt][2]), "r"(afr[mt][3]),
                      "r"(bw[i].x), "r"(bw[i].y));
            }
    }

    // epilogue: bias; B6 ntiles also add lut6a[a]; scatter to [s][b][j]
    int lane4 = (lane & 3) * 2;
    #pragma unroll
    for (int mt = 0; mt < 4; mt++) {
        int R0 = row0 + mt * 16 + (lane >> 2);
        int R1 = R0 + 8;
        int bb0 = R0 / SS, ss0 = R0 - bb0 * SS;
        int bb1 = R1 / SS, ss1 = R1 - bb1 * SS;
        int base0 = (ss0 * BB + bb0) * EE;
        int base1 = (ss1 * BB + bb1) * EE;
        int ia0 = a[R0], ia1 = a[R1];
        #pragma unroll
        for (int i = 0; i < 6; i++) {
            int n = (w * 6 + i) * 8 + lane4;
            float bx = g_bP[n], by = g_bP[n + 1];
            float c0 = acc[mt][i][0] + bx, c1 = acc[mt][i][1] + by;
            float c2 = acc[mt][i][2] + bx, c3 = acc[mt][i][3] + by;
            if (n < 128) {
                *reinterpret_cast<__half2*>(&g_P2[base0 + n]) = __floats2half2_rn(c0, c1);
                *reinterpret_cast<__half2*>(&g_P2[base1 + n]) = __floats2half2_rn(c2, c3);
            } else if (n < 256) {
                int nn = n - 128;
                *reinterpret_cast<__half2*>(&g_P3[base0 + nn]) = __floats2half2_rn(c0, c1);
                *reinterpret_cast<__half2*>(&g_P3[base1 + nn]) = __floats2half2_rn(c2, c3);
            } else {
                int nn = n - 256;
                c0 += g_lut6a[ia0 * 128 + nn];  c1 += g_lut6a[ia0 * 128 + nn + 1];
                c2 += g_lut6a[ia1 * 128 + nn];  c3 += g_lut6a[ia1 * 128 + nn + 1];
                *reinterpret_cast<__half2*>(&g_B6[base0 + nn]) = __floats2half2_rn(c0, c1);
                *reinterpret_cast<__half2*>(&g_B6[base1 + nn]) = __floats2half2_rn(c2, c3);
            }
        }
    }
}

// ---------------- scan kernel ----------------
// 512 threads: (j in [0,128), group g in {0..3}); 2 batch rows/CTA, row-interleaved half2.
// All weights fp16 in smem. Per step: phase1 (W2,W3,W6k over k), combine(sdft),
// phase2 (W4s,W5s over sdft), final (k update). Streams P2/P3/B6 prefetched 1 step ahead.
#define SB_W2 0
#define SB_W3 32768
#define SB_W4 65536
#define SB_W5 98304
#define SB_W6 131072
#define SB_K2 163840
#define SB_XC 164352
#define SB_KF 164864
#define SB_P2 165888
#define SB_P3 169984
#define SB_P6 174080
#define SB_P4 178176
#define SB_P5 182272
#define SB_TOT 186368

__global__ void __launch_bounds__(512, 1) k_scan(
    const int* __restrict__ a, const float* __restrict__ knowledge,
    float* __restrict__ out)
{
    extern __shared__ char sm[];
    uint2* W2s = reinterpret_cast<uint2*>(sm + SB_W2);
    uint2* W3s = reinterpret_cast<uint2*>(sm + SB_W3);
    uint2* W4s = reinterpret_cast<uint2*>(sm + SB_W4);
    uint2* W5s = reinterpret_cast<uint2*>(sm + SB_W5);
    uint2* W6s = reinterpret_cast<uint2*>(sm + SB_W6);
    __half2* k2  = reinterpret_cast<__half2*>(sm + SB_K2);
    __half2* xc2 = reinterpret_cast<__half2*>(sm + SB_XC);
    float2*  kf  = reinterpret_cast<float2*>(sm + SB_KF);
    float2*  pY2 = reinterpret_cast<float2*>(sm + SB_P2);
    float2*  pY3 = reinterpret_cast<float2*>(sm + SB_P3);
    float2*  pY6 = reinterpret_cast<float2*>(sm + SB_P6);
    float2*  pY4 = reinterpret_cast<float2*>(sm + SB_P4);
    float2*  pY5 = reinterpret_cast<float2*>(sm + SB_P5);
    const uint4* xk = reinterpret_cast<const uint4*>(sm + SB_K2);
    const uint4* xq = reinterpret_cast<const uint4*>(sm + SB_XC);

    int tid = threadIdx.x;
    int j = tid & 127, g = tid >> 7;
    int b0 = blockIdx.x * 2;

    for (int i = tid; i < 4096; i += 512) {
        W2s[i] = g_W2h[i]; W3s[i] = g_W3h[i]; W4s[i] = g_W4sh[i];
        W5s[i] = g_W5sh[i]; W6s[i] = g_W6kh[i];
    }

    // g0 per-step stream registers (current + next)
    __half P2c0, P2c1, P3c0, P3c1, B6c0, B6c1;
    __half P2n0, P2n1, P3n0, P3n1, B6n0, B6n1;
    int ia0c = 0, ia1c = 0, ia0n = 0, ia1n = 0;
    if (g == 0) {
        float kv = knowledge[j];
        kf[j] = make_float2(kv, kv);
        k2[j] = __floats2half2_rn(kv, kv);
        int r0 = b0 * EE + j, r1 = (b0 + 1) * EE + j;
        P2c0 = g_P2[r0]; P2c1 = g_P2[r1];
        P3c0 = g_P3[r0]; P3c1 = g_P3[r1];
        B6c0 = g_B6[r0]; B6c1 = g_B6[r1];
        ia0c = a[b0 * SS]; ia1c = a[(b0 + 1) * SS];
    }
    __syncthreads();

    float b2dummy = 0.f; (void)b2dummy;
    const int kb = g * 8;
    __half2 z = bits2h(0u);

    for (int s = 0; s < SS; s++) {
        int sn = (s + 1 < SS) ? s + 1 : 0;

        // ---- phase 1: y2,y3,y6k partials over k (K=128, 4-way split) ----
        {
            __half2 q2a=z,q2b=z,q2c=z,q2d=z, q3a=z,q3b=z,q3c=z,q3d=z, q6a=z,q6b=z,q6c=z,q6d=z;
            #pragma unroll
            for (int k4 = 0; k4 < 8; k4++) {
                int kk = kb + k4;
                uint4 x = xk[kk];
                uint2 w2 = W2s[kk * 128 + j];
                uint2 w3 = W3s[kk * 128 + j];
                uint2 w6 = W6s[kk * 128 + j];
                __half2 xa = bits2h(x.x), xb = bits2h(x.y), xc = bits2h(x.z), xd = bits2h(x.w);
                q2a = __hfma2(__low2half2(bits2h(w2.x)),  xa, q2a);
                q2b = __hfma2(__high2half2(bits2h(w2.x)), xb, q2b);
                q2c = __hfma2(__low2half2(bits2h(w2.y)),  xc, q2c);
                q2d = __hfma2(__high2half2(bits2h(w2.y)), xd, q2d);
                q3a = __hfma2(__low2half2(bits2h(w3.x)),  xa, q3a);
                q3b = __hfma2(__high2half2(bits2h(w3.x)), xb, q3b);
                q3c = __hfma2(__low2half2(bits2h(w3.y)),  xc, q3c);
                q3d = __hfma2(__high2half2(bits2h(w3.y)), xd, q3d);
                q6a = __hfma2(__low2half2(bits2h(w6.x)),  xa, q6a);
                q6b = __hfma2(__high2half2(bits2h(w6.x)), xb, q6b);
                q6c = __hfma2(__low2half2(bits2h(w6.y)),  xc, q6c);
                q6d = __hfma2(__high2half2(bits2h(w6.y)), xd, q6d);
            }
            pY2[g * 128 + j] = f2sum(q2a, q2b, q2c, q2d);
            pY3[g * 128 + j] = f2sum(q3a, q3b, q3c, q3d);
            pY6[g * 128 + j] = f2sum(q6a, q6b, q6c, q6d);
        }
        __syncthreads();

        // ---- combine: sdft; prefetch next-step streams ----
        if (g == 0) {
            float2 s2a = pY2[j], s2b = pY2[128 + j], s2c = pY2[256 + j], s2d = pY2[384 + j];
            float2 s3a = pY3[j], s3b = pY3[128 + j], s3c = pY3[256 + j], s3d = pY3[384 + j];
            float y20 = (s2a.x + s2b.x) + (s2c.x + s2d.x) - __half2float(P2c0);
            float y21 = (s2a.y + s2b.y) + (s2c.y + s2d.y) - __half2float(P2c1);
            float y30 = (s3a.x + s3b.x) + (s3c.x + s3d.x) - __half2float(P3c0);
            float y31 = (s3a.y + s3b.y) + (s3c.y + s3d.y) - __half2float(P3c1);
            xc2[j] = __floats2half2_rn(sigm(y20) * tanh_f(y30), sigm(y21) * tanh_f(y31));
            int r0 = (sn * BB + b0) * EE + j, r1 = (sn * BB + b0 + 1) * EE + j;
            P2n0 = g_P2[r0]; P2n1 = g_P2[r1];
            P3n0 = g_P3[r0]; P3n1 = g_P3[r1];
            B6n0 = g_B6[r0]; B6n1 = g_B6[r1];
            ia0n = a[b0 * SS + sn]; ia1n = a[(b0 + 1) * SS + sn];
        }
        __syncthreads();

        // ---- phase 2: y4,y5 sdft-half partials (K=128, 4-way split) ----
        {
            __half2 q4a=z,q4b=z,q4c=z,q4d=z, q5a=z,q5b=z,q5c=z,q5d=z;
            #pragma unroll
            for (int k4 = 0; k4 < 8; k4++) {
                int kk = kb + k4;
                uint4 x = xq[kk];
                uint2 w4 = W4s[kk * 128 + j];
                uint2 w5 = W5s[kk * 128 + j];
                __half2 xa = bits2h(x.x), xb = bits2h(x.y), xc = bits2h(x.z), xd = bits2h(x.w);
                q4a = __hfma2(__low2half2(bits2h(w4.x)),  xa, q4a);
                q4b = __hfma2(__high2half2(bits2h(w4.x)), xb, q4b);
                q4c = __hfma2(__low2half2(bits2h(w4.y)),  xc, q4c);
                q4d = __hfma2(__high2half2(bits2h(w4.y)), xd, q4d);
                q5a = __hfma2(__low2half2(bits2h(w5.x)),  xa, q5a);
                q5b = __hfma2(__high2half2(bits2h(w5.x)), xb, q5b);
                q5c = __hfma2(__low2half2(bits2h(w5.y)),  xc, q5c);
                q5d = __hfma2(__high2half2(bits2h(w5.y)), xd, q5d);
            }
            pY4[g * 128 + j] = f2sum(q4a, q4b, q4c, q4d);
            pY5[g * 128 + j] = f2sum(q5a, q5b, q5c, q5d);
        }
        __syncthreads();

        // ---- final: k update ----
        if (g == 0) {
            float2 s4a = pY4[j], s4b = pY4[128 + j], s4c = pY4[256 + j], s4d = pY4[384 + j];
            float2 s5a = pY5[j], s5b = pY5[128 + j], s5c = pY5[256 + j], s5d = pY5[384 + j];
            float2 s6a = pY6[j], s6b = pY6[128 + j], s6c = pY6[256 + j], s6d = pY6[384 + j];
            float y40 = (s4a.x + s4b.x) + (s4c.x + s4d.x) + g_lut4a[ia0c * 128 + j];
            float y41 = (s4a.y + s4b.y) + (s4c.y + s4d.y) + g_lut4a[ia1c * 128 + j];
            float y50 = (s5a.x + s5b.x) + (s5c.x + s5d.x) + g_lut5a[ia0c * 128 + j];
            float y51 = (s5a.y + s5b.y) + (s5c.y + s5d.y) + g_lut5a[ia1c * 128 + j];
            float pk0 = sigm(y40) * tanh_f(y50);
            float pk1 = sigm(y41) * tanh_f(y51);
            float y60 = (s6a.x + s6b.x) + (s6c.x + s6d.x) + __half2float(B6c0);
            float y61 = (s6a.y + s6b.y) + (s6c.y + s6d.y) + __half2float(B6c1);
            float g60 = sigm(y60), g61 = sigm(y61);
            float2 kv = kf[j];
            float kn0 = g60 * kv.x + (1.0f - g60) * pk0;
            float kn1 = g61 * kv.y + (1.0f - g61) * pk1;
            kf[j] = make_float2(kn0, kn1);
            k2[j] = __floats2half2_rn(kn0, kn1);
            // rotate prefetched streams
            P2c0 = P2n0; P2c1 = P2n1; P3c0 = P3n0; P3c1 = P3n1;
            B6c0 = B6n0; B6c1 = B6n1; ia0c = ia0n; ia1c = ia1n;
        }
        __syncthreads();
    }

    if (g == 0) {
        float2 kv = kf[j];
        out[b0 * EE + j]       = sigm(kv.x);
        out[(b0 + 1) * EE + j] = sigm(kv.y);
    }
}

// ---------------- launch ----------------
extern "C" void kernel_launch(void* const* d_in, const int* in_sizes, int n_in,
                              void* d_out, int out_size) {
    (void)in_sizes; (void)n_in; (void)out_size;
    const int*   c        = (const int*)d_in[1];
    const int*   sd       = (const int*)d_in[2];
    const int*   qd       = (const int*)d_in[3];
    const int*   a        = (const int*)d_in[4];
    const float* qemb     = (const float*)d_in[9];
    const float* c_tab    = (const float*)d_in[10];
    const float* sd_tab   = (const float*)d_in[11];
    const float* qd_tab   = (const float*)d_in[12];
    const float* a_tab    = (const float*)d_in[13];
    const float* know     = (const float*)d_in[14];
    const float* W1       = (const float*)d_in[15];
    const float* b1       = (const float*)d_in[16];
    const float* W2       = (const float*)d_in[17];
    const float* b2       = (const float*)d_in[18];
    const float* W3       = (const float*)d_in[19];
    const float* b3       = (const float*)d_in[20];
    const float* W4       = (const float*)d_in[21];
    const float* b4       = (const float*)d_in[22];
    const float* W5       = (const float*)d_in[23];
    const float* b5       = (const float*)d_in[24];
    const float* W6       = (const float*)d_in[25];
    const float* b6       = (const float*)d_in[26];
    float* out = (float*)d_out;

    cudaFuncSetAttribute(k_scan,   cudaFuncAttributeMaxDynamicSharedMemorySize, SB_TOT);
    cudaFuncSetAttribute(k_inputP, cudaFuncAttributeMaxDynamicSharedMemorySize, 65536);

    prep1<<<597, 256>>>(W1, W2, W3, W4, W5, W6, b1, b2, b3, b4, b5, b6, a_tab);
    prep2<<<192, 256>>>(W6);
    k_inputP<<<2000, 256, 65536>>>(qemb, c, sd, qd, c_tab, sd_tab, qd_tab, a);
    k_scan<<<128, 512, SB_TOT>>>(a, know, out);
}